// round 1
// baseline (speedup 1.0000x reference)
#include <cuda_runtime.h>
#include <math.h>

#define BATCH 256
#define NHEAD 16
#define HDIM  128
#define HID   2048        // NHEAD * HDIM
#define N3    6144        // 3 * HID

// Scratch: activated gates and projections, [B, HID] each (b*HID + h*D + d)
__device__ __align__(16) float g_i[BATCH * HID];
__device__ __align__(16) float g_f[BATCH * HID];
__device__ __align__(16) float g_o[BATCH * HID];
__device__ __align__(16) float g_q[BATCH * HID];
__device__ __align__(16) float g_k[BATCH * HID];
__device__ __align__(16) float g_v[BATCH * HID];

// ---------------------------------------------------------------------------
// Kernel 1: gates = x @ W_i + b_i  -> exp / exp / sigmoid -> g_i, g_f, g_o
// M=256, N=6144, K=2048. 64x64 tile, 256 threads, 4x4 per thread.
// ---------------------------------------------------------------------------
__global__ __launch_bounds__(256) void gates_kernel(
    const float* __restrict__ x, const float* __restrict__ W,
    const float* __restrict__ bias)
{
    __shared__ float As[64][16];   // [m][k]
    __shared__ float Bs[16][64];   // [k][n]

    const int tid = threadIdx.x;
    const int tx = tid & 15;       // n dir
    const int ty = tid >> 4;       // m dir
    const int n0 = blockIdx.x * 64;
    const int m0 = blockIdx.y * 64;

    const int am = m0 + (tid >> 2);
    const int ak = (tid & 3) * 4;
    const int bk = tid >> 4;
    const int bn = (tid & 15) * 4;

    float acc[4][4] = {};

    for (int k0 = 0; k0 < HID; k0 += 16) {
        float4 av = *(const float4*)(x + (size_t)am * HID + k0 + ak);
        float4 bv = *(const float4*)(W + (size_t)(k0 + bk) * N3 + n0 + bn);
        ((float4*)As)[tid] = av;                 // As[tid/4][(tid%4)*4..]
        *(float4*)(&Bs[bk][bn]) = bv;
        __syncthreads();

        #pragma unroll
        for (int kk = 0; kk < 16; kk++) {
            float a0 = As[ty * 4 + 0][kk];
            float a1 = As[ty * 4 + 1][kk];
            float a2 = As[ty * 4 + 2][kk];
            float a3 = As[ty * 4 + 3][kk];
            float4 b4 = *(float4*)(&Bs[kk][tx * 4]);
            acc[0][0] += a0 * b4.x; acc[0][1] += a0 * b4.y; acc[0][2] += a0 * b4.z; acc[0][3] += a0 * b4.w;
            acc[1][0] += a1 * b4.x; acc[1][1] += a1 * b4.y; acc[1][2] += a1 * b4.z; acc[1][3] += a1 * b4.w;
            acc[2][0] += a2 * b4.x; acc[2][1] += a2 * b4.y; acc[2][2] += a2 * b4.z; acc[2][3] += a2 * b4.w;
            acc[3][0] += a3 * b4.x; acc[3][1] += a3 * b4.y; acc[3][2] += a3 * b4.z; acc[3][3] += a3 * b4.w;
        }
        __syncthreads();
    }

    // epilogue: bias + activation; whole block is one gate class (2048 % 64 == 0)
    const int cls = n0 >> 11;                     // 0:i 1:f 2:o
    const int cb = n0 & 2047;
    float* outp = (cls == 0) ? g_i : ((cls == 1) ? g_f : g_o);

    #pragma unroll
    for (int i = 0; i < 4; i++) {
        const int m = m0 + ty * 4 + i;
        float v[4];
        #pragma unroll
        for (int j = 0; j < 4; j++) {
            float t = acc[i][j] + bias[n0 + tx * 4 + j];
            v[j] = (cls == 2) ? (1.0f / (1.0f + expf(-t))) : expf(t);
        }
        float4 r = make_float4(v[0], v[1], v[2], v[3]);
        *(float4*)(outp + (size_t)m * HID + cb + tx * 4) = r;
    }
}

// ---------------------------------------------------------------------------
// Kernel 2: per-head qkv = x_h @ W_qkv[h] + b_qkv[h]  (M=64 batch tile,
// N=64 tile of 384, K=128). Grid (6, 4, 16).
// ---------------------------------------------------------------------------
__global__ __launch_bounds__(256) void qkv_kernel(
    const float* __restrict__ x, const float* __restrict__ Wq,
    const float* __restrict__ bq)
{
    __shared__ float As[64][16];
    __shared__ float Bs[16][64];

    const int tid = threadIdx.x;
    const int tx = tid & 15;
    const int ty = tid >> 4;
    const int head = blockIdx.z;
    const int n0 = blockIdx.x * 64;      // 0..320
    const int m0 = blockIdx.y * 64;

    const int am = m0 + (tid >> 2);
    const int ak = (tid & 3) * 4;
    const int bk = tid >> 4;
    const int bn = (tid & 15) * 4;

    const float* Wh = Wq + (size_t)head * HDIM * 384;

    float acc[4][4] = {};

    for (int k0 = 0; k0 < HDIM; k0 += 16) {
        float4 av = *(const float4*)(x + (size_t)am * HID + head * HDIM + k0 + ak);
        float4 bv = *(const float4*)(Wh + (size_t)(k0 + bk) * 384 + n0 + bn);
        ((float4*)As)[tid] = av;
        *(float4*)(&Bs[bk][bn]) = bv;
        __syncthreads();

        #pragma unroll
        for (int kk = 0; kk < 16; kk++) {
            float a0 = As[ty * 4 + 0][kk];
            float a1 = As[ty * 4 + 1][kk];
            float a2 = As[ty * 4 + 2][kk];
            float a3 = As[ty * 4 + 3][kk];
            float4 b4 = *(float4*)(&Bs[kk][tx * 4]);
            acc[0][0] += a0 * b4.x; acc[0][1] += a0 * b4.y; acc[0][2] += a0 * b4.z; acc[0][3] += a0 * b4.w;
            acc[1][0] += a1 * b4.x; acc[1][1] += a1 * b4.y; acc[1][2] += a1 * b4.z; acc[1][3] += a1 * b4.w;
            acc[2][0] += a2 * b4.x; acc[2][1] += a2 * b4.y; acc[2][2] += a2 * b4.z; acc[2][3] += a2 * b4.w;
            acc[3][0] += a3 * b4.x; acc[3][1] += a3 * b4.y; acc[3][2] += a3 * b4.z; acc[3][3] += a3 * b4.w;
        }
        __syncthreads();
    }

    const int cls = n0 >> 7;                 // 0:q 1:k 2:v
    const int colb = (n0 & 127) + tx * 4;    // 0..124 within head dim
    float* outp = (cls == 0) ? g_q : ((cls == 1) ? g_k : g_v);
    const float kscale = 0.08838834764831845f;   // 1/sqrt(128)

    #pragma unroll
    for (int i = 0; i < 4; i++) {
        const int m = m0 + ty * 4 + i;
        float v[4];
        #pragma unroll
        for (int j = 0; j < 4; j++) {
            float t = acc[i][j] + bq[head * 384 + n0 + tx * 4 + j];
            if (cls == 1) t *= kscale;
            v[j] = t;
        }
        float4 r = make_float4(v[0], v[1], v[2], v[3]);
        *(float4*)(outp + (size_t)m * HID + head * HDIM + colb) = r;
    }
}

// ---------------------------------------------------------------------------
// Kernel 3: fused state update. One block (128 thr) per (b,h).
//   n_new = f*n + i*k;  denom = max(|n_new . q|, 1)
//   h_new = o * (C @ q) / denom
//   C_new = f[:,None]*C + (i*v)[:,None]*k[None,:]
// C streamed once in, once out (memory-roofline bound).
// ---------------------------------------------------------------------------
__global__ __launch_bounds__(128) void state_kernel(
    const float* __restrict__ Cin, const float* __restrict__ nin,
    float* __restrict__ out_h, float* __restrict__ out_C,
    float* __restrict__ out_n)
{
    __shared__ float q_s[128], k_s[128];
    __shared__ float f_s[128], a_s[128], o_s[128];
    __shared__ float red[4];
    __shared__ float s_inv;

    const int t = threadIdx.x;
    const int w = t >> 5;
    const int lane = t & 31;
    const int vo = blockIdx.x * HDIM;      // blockIdx.x == b*NH + h

    float iv = g_i[vo + t], fv = g_f[vo + t], ov = g_o[vo + t];
    float qv = g_q[vo + t], kv = g_k[vo + t], vv = g_v[vo + t];
    float nv = nin[vo + t];

    float nn = fv * nv + iv * kv;
    out_n[vo + t] = nn;

    q_s[t] = qv; k_s[t] = kv;
    f_s[t] = fv; a_s[t] = iv * vv; o_s[t] = ov;

    float p = nn * qv;
    #pragma unroll
    for (int off = 16; off; off >>= 1) p += __shfl_xor_sync(0xffffffffu, p, off);
    if (lane == 0) red[w] = p;
    __syncthreads();
    if (t == 0) {
        float dot = red[0] + red[1] + red[2] + red[3];
        s_inv = 1.0f / fmaxf(fabsf(dot), 1.0f);
    }
    __syncthreads();
    const float inv = s_inv;

    const float4 q4 = ((const float4*)q_s)[lane];
    const float4 k4 = ((const float4*)k_s)[lane];
    const float4* C4 = (const float4*)(Cin + (size_t)blockIdx.x * HDIM * HDIM);
    float4* O4 = (float4*)(out_C + (size_t)blockIdx.x * HDIM * HDIM);

    #pragma unroll 4
    for (int r = 0; r < 32; r++) {
        const int d = (w << 5) + r;
        float4 c = C4[d * 32 + lane];
        float part = c.x * q4.x + c.y * q4.y + c.z * q4.z + c.w * q4.w;
        const float fd = f_s[d], ad = a_s[d];
        float4 cn;
        cn.x = fd * c.x + ad * k4.x;
        cn.y = fd * c.y + ad * k4.y;
        cn.z = fd * c.z + ad * k4.z;
        cn.w = fd * c.w + ad * k4.w;
        O4[d * 32 + lane] = cn;
        #pragma unroll
        for (int off = 16; off; off >>= 1)
            part += __shfl_xor_sync(0xffffffffu, part, off);
        if (lane == 0) out_h[vo + d] = o_s[d] * part * inv;
    }
}

// ---------------------------------------------------------------------------
// Launch. Inputs (metadata order): x, h(unused), C, n, W_i, b_i, W_qkv, b_qkv
// Output: [h_new (B*HID) | C_new (B*NH*D*D) | n_new (B*NH*D)]
// ---------------------------------------------------------------------------
extern "C" void kernel_launch(void* const* d_in, const int* in_sizes, int n_in,
                              void* d_out, int out_size)
{
    const float* x     = (const float*)d_in[0];
    const float* C     = (const float*)d_in[2];
    const float* n     = (const float*)d_in[3];
    const float* W_i   = (const float*)d_in[4];
    const float* b_i   = (const float*)d_in[5];
    const float* W_qkv = (const float*)d_in[6];
    const float* b_qkv = (const float*)d_in[7];

    float* out   = (float*)d_out;
    float* out_h = out;
    float* out_C = out + (size_t)BATCH * HID;
    float* out_n = out_C + (size_t)BATCH * NHEAD * HDIM * HDIM;

    gates_kernel<<<dim3(N3 / 64, BATCH / 64), 256>>>(x, W_i, b_i);
    qkv_kernel<<<dim3(384 / 64, BATCH / 64, NHEAD), 256>>>(x, W_qkv, b_qkv);
    state_kernel<<<BATCH * NHEAD, 128>>>(C, n, out_h, out_C, out_n);
}

// round 4
// speedup vs baseline: 1.1645x; 1.1645x over previous
#include <cuda_runtime.h>
#include <cuda_bf16.h>
#include <cstdint>
#include <math.h>

#define BATCH 256
#define NHEAD 16
#define HDIM  128
#define HID   2048        // NHEAD * HDIM
#define N3    6144        // 3 * HID

// Scratch: activated gates and projections, [B, HID] each
__device__ __align__(16) float g_i[BATCH * HID];
__device__ __align__(16) float g_f[BATCH * HID];
__device__ __align__(16) float g_o[BATCH * HID];
__device__ __align__(16) float g_q[BATCH * HID];
__device__ __align__(16) float g_k[BATCH * HID];
__device__ __align__(16) float g_v[BATCH * HID];

// Split-precision scratch (bf16 hi/lo)
__device__ __align__(16) __nv_bfloat16 s_xh[BATCH * HID];
__device__ __align__(16) __nv_bfloat16 s_xl[BATCH * HID];
__device__ __align__(16) __nv_bfloat16 s_wh[(size_t)N3 * HID];   // W_i^T [6144,2048]
__device__ __align__(16) __nv_bfloat16 s_wl[(size_t)N3 * HID];

// ---------------------------------------------------------------------------
// Split x -> bf16 hi/lo
// ---------------------------------------------------------------------------
__global__ __launch_bounds__(256) void split_x_kernel(const float* __restrict__ x)
{
    int idx = blockIdx.x * 256 + threadIdx.x;
    float v = x[idx];
    __nv_bfloat16 hi = __float2bfloat16(v);
    float lo = v - __bfloat162float(hi);
    s_xh[idx] = hi;
    s_xl[idx] = __float2bfloat16(lo);
}

// ---------------------------------------------------------------------------
// Split + transpose W_i [2048,6144] -> Wt hi/lo [6144,2048]
// ---------------------------------------------------------------------------
__global__ __launch_bounds__(256) void splitT_w_kernel(const float* __restrict__ W)
{
    __shared__ float tile[32][33];
    const int n0 = blockIdx.x * 32;
    const int k0 = blockIdx.y * 32;
    const int tx = threadIdx.x & 31;
    const int ty = threadIdx.x >> 5;   // 0..7

    #pragma unroll
    for (int j = 0; j < 4; j++)
        tile[ty + j * 8][tx] = W[(size_t)(k0 + ty + j * 8) * N3 + n0 + tx];
    __syncthreads();

    #pragma unroll
    for (int j = 0; j < 4; j++) {
        float v = tile[tx][ty + j * 8];
        __nv_bfloat16 hi = __float2bfloat16(v);
        float lo = v - __bfloat162float(hi);
        size_t o = (size_t)(n0 + ty + j * 8) * HID + k0 + tx;
        s_wh[o] = hi;
        s_wl[o] = __float2bfloat16(lo);
    }
}

// ---------------------------------------------------------------------------
// PTX helpers (sm_80-compatible: cp.async + ldmatrix + mma.sync)
// ---------------------------------------------------------------------------
__device__ __forceinline__ void cp_async16(uint32_t dst, const void* src) {
    asm volatile("cp.async.cg.shared.global [%0], [%1], 16;"
                 :: "r"(dst), "l"(src));
}
__device__ __forceinline__ void cp_commit() {
    asm volatile("cp.async.commit_group;");
}

__device__ __forceinline__ void ldm_x4(uint32_t* r, uint32_t addr) {
    asm volatile("ldmatrix.sync.aligned.m8n8.x4.shared.b16 {%0,%1,%2,%3}, [%4];"
                 : "=r"(r[0]), "=r"(r[1]), "=r"(r[2]), "=r"(r[3]) : "r"(addr));
}

__device__ __forceinline__ void mma16816(float* c, const uint32_t* a, const uint32_t* b) {
    asm volatile(
        "mma.sync.aligned.m16n8k16.row.col.f32.bf16.bf16.f32 "
        "{%0,%1,%2,%3}, {%4,%5,%6,%7}, {%8,%9}, {%0,%1,%2,%3};"
        : "+f"(c[0]), "+f"(c[1]), "+f"(c[2]), "+f"(c[3])
        : "r"(a[0]), "r"(a[1]), "r"(a[2]), "r"(a[3]), "r"(b[0]), "r"(b[1]));
}

// ---------------------------------------------------------------------------
// Gates GEMM: D = Xh@Wh^T + Xh@Wl^T + Xl@Wh^T  (bf16x3 split precision)
// CTA tile 128x128, 256 threads (8 warps 4Mx2N, warp tile 32x64), BK=32,
// double-buffered cp.async. Fused bias + exp/sigmoid epilogue.
// NOTE: B is staged [N][K] (K contiguous) == transpose of the logical [K,N]
// operand, so the B fragment comes from NON-trans ldmatrix.
// ---------------------------------------------------------------------------
#define SSTRIDE 40            // bf16 elements per smem row (80B, 16B aligned)
#define NIT 192               // 3 terms * 64 chunks of K=32

__global__ __launch_bounds__(256) void gates_mma_kernel(const float* __restrict__ bias)
{
    __shared__ __nv_bfloat16 As[2][128 * SSTRIDE];
    __shared__ __nv_bfloat16 Bs[2][128 * SSTRIDE];

    const int tid = threadIdx.x;
    const int lane = tid & 31;
    const int wid = tid >> 5;
    const int warp_m = (wid & 3) * 32;     // 0,32,64,96
    const int warp_n = (wid >> 2) * 64;    // 0,64
    const int n0 = blockIdx.x * 128;
    const int m0 = blockIdx.y * 128;

    // cp.async staging: 512 16B segments per matrix, 2 per thread
    const int r_a = tid >> 2;              // row 0..63  (+64 on second seg)
    const int s_a = tid & 3;               // 16B segment within 64B of K=32

    const uint32_t sAs = (uint32_t)__cvta_generic_to_shared(As);
    const uint32_t sBs = (uint32_t)__cvta_generic_to_shared(Bs);

    float c[2][8][4];
    #pragma unroll
    for (int i = 0; i < 2; i++)
        #pragma unroll
        for (int j = 0; j < 8; j++)
            #pragma unroll
            for (int q = 0; q < 4; q++) c[i][j][q] = 0.0f;

    auto load_chunk = [&](int it, int buf) {
        const int term = it >> 6;
        const int k0 = (it & 63) << 5;
        const __nv_bfloat16* Ap = (term < 2) ? s_xh : s_xl;
        const __nv_bfloat16* Bp = (term == 1) ? s_wl : s_wh;
        #pragma unroll
        for (int h = 0; h < 2; h++) {
            const int row = r_a + h * 64;
            const uint32_t doff = (uint32_t)(row * SSTRIDE + s_a * 8) * 2;
            cp_async16(sAs + buf * (128 * SSTRIDE * 2) + doff,
                       Ap + (size_t)(m0 + row) * HID + k0 + s_a * 8);
            cp_async16(sBs + buf * (128 * SSTRIDE * 2) + doff,
                       Bp + (size_t)(n0 + row) * HID + k0 + s_a * 8);
        }
        cp_commit();
    };

    load_chunk(0, 0);

    for (int it = 0; it < NIT; ++it) {
        const int buf = it & 1;
        if (it + 1 < NIT) {
            load_chunk(it + 1, buf ^ 1);
            asm volatile("cp.async.wait_group 1;");
        } else {
            asm volatile("cp.async.wait_group 0;");
        }
        __syncthreads();

        const uint32_t Ab = sAs + buf * (128 * SSTRIDE * 2);
        const uint32_t Bb = sBs + buf * (128 * SSTRIDE * 2);

        #pragma unroll
        for (int kk = 0; kk < 32; kk += 16) {
            uint32_t a[2][4];
            #pragma unroll
            for (int slab = 0; slab < 2; slab++) {
                const int row = warp_m + slab * 16 + (lane & 15);
                const int col = kk + ((lane >> 4) << 3);
                ldm_x4(a[slab], Ab + (uint32_t)(row * SSTRIDE + col) * 2);
            }
            uint32_t b[8][2];
            #pragma unroll
            for (int nb = 0; nb < 4; nb++) {
                const int g = lane >> 3;
                const int nrow = warp_n + nb * 16 + ((g >> 1) << 3) + (lane & 7);
                const int col = kk + ((g & 1) << 3);
                uint32_t rr[4];
                ldm_x4(rr, Bb + (uint32_t)(nrow * SSTRIDE + col) * 2);
                b[nb * 2 + 0][0] = rr[0]; b[nb * 2 + 0][1] = rr[1];
                b[nb * 2 + 1][0] = rr[2]; b[nb * 2 + 1][1] = rr[3];
            }
            #pragma unroll
            for (int slab = 0; slab < 2; slab++)
                #pragma unroll
                for (int j = 0; j < 8; j++)
                    mma16816(c[slab][j], a[slab], b[j]);
        }
        __syncthreads();
    }

    // Epilogue: bias + activation; CTA's n-range lies in one gate class
    const int cls = n0 >> 11;                 // 0:i 1:f 2:o
    float* outp = (cls == 0) ? g_i : ((cls == 1) ? g_f : g_o);
    const int cb = n0 & 2047;

    #pragma unroll
    for (int slab = 0; slab < 2; slab++) {
        const int mrow = m0 + warp_m + slab * 16 + (lane >> 2);
        #pragma unroll
        for (int j = 0; j < 8; j++) {
            const int col = warp_n + j * 8 + ((lane & 3) << 1);
            const float b0 = bias[n0 + col], b1 = bias[n0 + col + 1];
            float t0 = c[slab][j][0] + b0, t1 = c[slab][j][1] + b1;
            float t2 = c[slab][j][2] + b0, t3 = c[slab][j][3] + b1;
            float2 v0, v1;
            if (cls == 2) {
                v0.x = 1.0f / (1.0f + expf(-t0));
                v0.y = 1.0f / (1.0f + expf(-t1));
                v1.x = 1.0f / (1.0f + expf(-t2));
                v1.y = 1.0f / (1.0f + expf(-t3));
            } else {
                v0.x = expf(t0); v0.y = expf(t1);
                v1.x = expf(t2); v1.y = expf(t3);
            }
            *(float2*)(outp + (size_t)mrow * HID + cb + col) = v0;
            *(float2*)(outp + (size_t)(mrow + 8) * HID + cb + col) = v1;
        }
    }
}

// ---------------------------------------------------------------------------
// Kernel 2: per-head qkv = x_h @ W_qkv[h] + b_qkv[h]  (SIMT fp32; small)
// ---------------------------------------------------------------------------
__global__ __launch_bounds__(256) void qkv_kernel(
    const float* __restrict__ x, const float* __restrict__ Wq,
    const float* __restrict__ bq)
{
    __shared__ float As2[64][16];
    __shared__ float Bs2[16][64];

    const int tid = threadIdx.x;
    const int tx = tid & 15;
    const int ty = tid >> 4;
    const int head = blockIdx.z;
    const int n0 = blockIdx.x * 64;
    const int m0 = blockIdx.y * 64;

    const int am = m0 + (tid >> 2);
    const int ak = (tid & 3) * 4;
    const int bk = tid >> 4;
    const int bn = (tid & 15) * 4;

    const float* Wh = Wq + (size_t)head * HDIM * 384;

    float acc[4][4] = {};

    for (int k0 = 0; k0 < HDIM; k0 += 16) {
        float4 av = *(const float4*)(x + (size_t)am * HID + head * HDIM + k0 + ak);
        float4 bv = *(const float4*)(Wh + (size_t)(k0 + bk) * 384 + n0 + bn);
        ((float4*)As2)[tid] = av;
        *(float4*)(&Bs2[bk][bn]) = bv;
        __syncthreads();

        #pragma unroll
        for (int kk = 0; kk < 16; kk++) {
            float a0 = As2[ty * 4 + 0][kk];
            float a1 = As2[ty * 4 + 1][kk];
            float a2 = As2[ty * 4 + 2][kk];
            float a3 = As2[ty * 4 + 3][kk];
            float4 b4 = *(float4*)(&Bs2[kk][tx * 4]);
            acc[0][0] += a0 * b4.x; acc[0][1] += a0 * b4.y; acc[0][2] += a0 * b4.z; acc[0][3] += a0 * b4.w;
            acc[1][0] += a1 * b4.x; acc[1][1] += a1 * b4.y; acc[1][2] += a1 * b4.z; acc[1][3] += a1 * b4.w;
            acc[2][0] += a2 * b4.x; acc[2][1] += a2 * b4.y; acc[2][2] += a2 * b4.z; acc[2][3] += a2 * b4.w;
            acc[3][0] += a3 * b4.x; acc[3][1] += a3 * b4.y; acc[3][2] += a3 * b4.z; acc[3][3] += a3 * b4.w;
        }
        __syncthreads();
    }

    const int cls = n0 >> 7;
    const int colb = (n0 & 127) + tx * 4;
    float* outp = (cls == 0) ? g_q : ((cls == 1) ? g_k : g_v);
    const float kscale = 0.08838834764831845f;   // 1/sqrt(128)

    #pragma unroll
    for (int i = 0; i < 4; i++) {
        const int m = m0 + ty * 4 + i;
        float v[4];
        #pragma unroll
        for (int jj = 0; jj < 4; jj++) {
            float t = acc[i][jj] + bq[head * 384 + n0 + tx * 4 + jj];
            if (cls == 1) t *= kscale;
            v[jj] = t;
        }
        float4 rr = make_float4(v[0], v[1], v[2], v[3]);
        *(float4*)(outp + (size_t)m * HID + head * HDIM + colb) = rr;
    }
}

// ---------------------------------------------------------------------------
// Kernel 3: fused state update (memory-roofline bound on C traffic)
// ---------------------------------------------------------------------------
__global__ __launch_bounds__(128) void state_kernel(
    const float* __restrict__ Cin, const float* __restrict__ nin,
    float* __restrict__ out_h, float* __restrict__ out_C,
    float* __restrict__ out_n)
{
    __shared__ float q_s[128], k_s[128];
    __shared__ float f_s[128], a_s[128], o_s[128];
    __shared__ float red[4];
    __shared__ float s_inv;

    const int t = threadIdx.x;
    const int w = t >> 5;
    const int lane = t & 31;
    const int vo = blockIdx.x * HDIM;

    float iv = g_i[vo + t], fv = g_f[vo + t], ov = g_o[vo + t];
    float qv = g_q[vo + t], kv = g_k[vo + t], vv = g_v[vo + t];
    float nv = nin[vo + t];

    float nn = fv * nv + iv * kv;
    out_n[vo + t] = nn;

    q_s[t] = qv; k_s[t] = kv;
    f_s[t] = fv; a_s[t] = iv * vv; o_s[t] = ov;

    float p = nn * qv;
    #pragma unroll
    for (int off = 16; off; off >>= 1) p += __shfl_xor_sync(0xffffffffu, p, off);
    if (lane == 0) red[w] = p;
    __syncthreads();
    if (t == 0) {
        float dot = red[0] + red[1] + red[2] + red[3];
        s_inv = 1.0f / fmaxf(fabsf(dot), 1.0f);
    }
    __syncthreads();
    const float inv = s_inv;

    const float4 q4 = ((const float4*)q_s)[lane];
    const float4 k4 = ((const float4*)k_s)[lane];
    const float4* C4 = (const float4*)(Cin + (size_t)blockIdx.x * HDIM * HDIM);
    float4* O4 = (float4*)(out_C + (size_t)blockIdx.x * HDIM * HDIM);

    #pragma unroll 4
    for (int r = 0; r < 32; r++) {
        const int d = (w << 5) + r;
        float4 cc = C4[d * 32 + lane];
        float part = cc.x * q4.x + cc.y * q4.y + cc.z * q4.z + cc.w * q4.w;
        const float fd = f_s[d], ad = a_s[d];
        float4 cn;
        cn.x = fd * cc.x + ad * k4.x;
        cn.y = fd * cc.y + ad * k4.y;
        cn.z = fd * cc.z + ad * k4.z;
        cn.w = fd * cc.w + ad * k4.w;
        O4[d * 32 + lane] = cn;
        #pragma unroll
        for (int off = 16; off; off >>= 1)
            part += __shfl_xor_sync(0xffffffffu, part, off);
        if (lane == 0) out_h[vo + d] = o_s[d] * part * inv;
    }
}

// ---------------------------------------------------------------------------
// Launch
// ---------------------------------------------------------------------------
extern "C" void kernel_launch(void* const* d_in, const int* in_sizes, int n_in,
                              void* d_out, int out_size)
{
    const float* x     = (const float*)d_in[0];
    const float* C     = (const float*)d_in[2];
    const float* n     = (const float*)d_in[3];
    const float* W_i   = (const float*)d_in[4];
    const float* b_i   = (const float*)d_in[5];
    const float* W_qkv = (const float*)d_in[6];
    const float* b_qkv = (const float*)d_in[7];

    float* out   = (float*)d_out;
    float* out_h = out;
    float* out_C = out + (size_t)BATCH * HID;
    float* out_n = out_C + (size_t)BATCH * NHEAD * HDIM * HDIM;

    split_x_kernel<<<(BATCH * HID) / 256, 256>>>(x);
    splitT_w_kernel<<<dim3(N3 / 32, HID / 32), 256>>>(W_i);
    gates_mma_kernel<<<dim3(N3 / 128, BATCH / 128), 256>>>(b_i);
    qkv_kernel<<<dim3(384 / 64, BATCH / 64, NHEAD), 256>>>(x, W_qkv, b_qkv);
    state_kernel<<<BATCH * NHEAD, 128>>>(C, n, out_h, out_C, out_n);
}

// round 6
// speedup vs baseline: 1.2826x; 1.1014x over previous
#include <cuda_runtime.h>
#include <cuda_bf16.h>
#include <cstdint>
#include <math.h>

#define BATCH 256
#define NHEAD 16
#define HDIM  128
#define HID   2048        // NHEAD * HDIM
#define N3    6144        // 3 * HID

// Scratch: activated gates and projections, [B, HID] each
__device__ __align__(16) float g_i[BATCH * HID];
__device__ __align__(16) float g_f[BATCH * HID];
__device__ __align__(16) float g_o[BATCH * HID];
__device__ __align__(16) float g_q[BATCH * HID];
__device__ __align__(16) float g_k[BATCH * HID];
__device__ __align__(16) float g_v[BATCH * HID];

// Split-precision scratch (bf16 hi/lo)
__device__ __align__(16) __nv_bfloat16 s_xh[BATCH * HID];
__device__ __align__(16) __nv_bfloat16 s_xl[BATCH * HID];
__device__ __align__(16) __nv_bfloat16 s_wh[(size_t)N3 * HID];   // W_i^T [6144,2048]
__device__ __align__(16) __nv_bfloat16 s_wl[(size_t)N3 * HID];

// ---------------------------------------------------------------------------
// Split x -> bf16 hi/lo
// ---------------------------------------------------------------------------
__global__ __launch_bounds__(256) void split_x_kernel(const float* __restrict__ x)
{
    int idx = blockIdx.x * 256 + threadIdx.x;
    float v = x[idx];
    __nv_bfloat16 hi = __float2bfloat16(v);
    float lo = v - __bfloat162float(hi);
    s_xh[idx] = hi;
    s_xl[idx] = __float2bfloat16(lo);
}

// ---------------------------------------------------------------------------
// Split + transpose W_i [2048,6144] -> Wt hi/lo [6144,2048]
// ---------------------------------------------------------------------------
__global__ __launch_bounds__(256) void splitT_w_kernel(const float* __restrict__ W)
{
    __shared__ float tile[32][33];
    const int n0 = blockIdx.x * 32;
    const int k0 = blockIdx.y * 32;
    const int tx = threadIdx.x & 31;
    const int ty = threadIdx.x >> 5;   // 0..7

    #pragma unroll
    for (int j = 0; j < 4; j++)
        tile[ty + j * 8][tx] = W[(size_t)(k0 + ty + j * 8) * N3 + n0 + tx];
    __syncthreads();

    #pragma unroll
    for (int j = 0; j < 4; j++) {
        float v = tile[tx][ty + j * 8];
        __nv_bfloat16 hi = __float2bfloat16(v);
        float lo = v - __bfloat162float(hi);
        size_t o = (size_t)(n0 + ty + j * 8) * HID + k0 + tx;
        s_wh[o] = hi;
        s_wl[o] = __float2bfloat16(lo);
    }
}

// ---------------------------------------------------------------------------
// PTX helpers (sm_80-compatible: cp.async + ldmatrix + mma.sync)
// ---------------------------------------------------------------------------
__device__ __forceinline__ void cp_async16(uint32_t dst, const void* src) {
    asm volatile("cp.async.cg.shared.global [%0], [%1], 16;"
                 :: "r"(dst), "l"(src));
}
__device__ __forceinline__ void cp_commit() {
    asm volatile("cp.async.commit_group;");
}

__device__ __forceinline__ void ldm_x4(uint32_t* r, uint32_t addr) {
    asm volatile("ldmatrix.sync.aligned.m8n8.x4.shared.b16 {%0,%1,%2,%3}, [%4];"
                 : "=r"(r[0]), "=r"(r[1]), "=r"(r[2]), "=r"(r[3]) : "r"(addr));
}

__device__ __forceinline__ void mma16816(float* c, const uint32_t* a, const uint32_t* b) {
    asm volatile(
        "mma.sync.aligned.m16n8k16.row.col.f32.bf16.bf16.f32 "
        "{%0,%1,%2,%3}, {%4,%5,%6,%7}, {%8,%9}, {%0,%1,%2,%3};"
        : "+f"(c[0]), "+f"(c[1]), "+f"(c[2]), "+f"(c[3])
        : "r"(a[0]), "r"(a[1]), "r"(a[2]), "r"(a[3]), "r"(b[0]), "r"(b[1]));
}

// ---------------------------------------------------------------------------
// Gates GEMM: D = Xh@Wh^T + Xl@Wh^T + Xh@Wl^T  (bf16x3 split precision)
// CTA tile 128x128, 256 threads (8 warps 4Mx2N, warp tile 32x64).
// BK=64 stages, 3-stage cp.async ring (dynamic smem), register
// double-buffered fragments. Fused bias + exp/sigmoid epilogue.
// B staged [N][K] (K contiguous) -> non-trans ldmatrix.
// ---------------------------------------------------------------------------
#define SST 72                    // bf16 elems per smem row (144B = 9*16B)
#define STAGE_BYTES (128 * SST * 2)   // 18432 per matrix
#define NSTAGES 96                // 3 terms * 32 chunks of K=64
#define DSMEM (3 * 2 * STAGE_BYTES)   // 110592 B

__device__ __forceinline__ void load_frags(
    uint32_t Ab, uint32_t Bb, int kk, int warp_m, int warp_n, int lane,
    uint32_t af[2][4], uint32_t bf[8][2])
{
    #pragma unroll
    for (int slab = 0; slab < 2; slab++) {
        const int row = warp_m + slab * 16 + (lane & 15);
        const int col = kk + ((lane >> 4) << 3);
        ldm_x4(af[slab], Ab + (uint32_t)(row * SST + col) * 2);
    }
    const int g = lane >> 3;
    #pragma unroll
    for (int nb = 0; nb < 4; nb++) {
        const int nrow = warp_n + nb * 16 + ((g >> 1) << 3) + (lane & 7);
        const int col = kk + ((g & 1) << 3);
        uint32_t rr[4];
        ldm_x4(rr, Bb + (uint32_t)(nrow * SST + col) * 2);
        bf[nb * 2 + 0][0] = rr[0]; bf[nb * 2 + 0][1] = rr[1];
        bf[nb * 2 + 1][0] = rr[2]; bf[nb * 2 + 1][1] = rr[3];
    }
}

__global__ __launch_bounds__(256, 1) void gates_mma_kernel(const float* __restrict__ bias)
{
    extern __shared__ __nv_bfloat16 smem[];

    const int tid = threadIdx.x;
    const int lane = tid & 31;
    const int wid = tid >> 5;
    const int warp_m = (wid & 3) * 32;     // 0,32,64,96
    const int warp_n = (wid >> 2) * 64;    // 0,64
    const int n0 = blockIdx.x * 128;
    const int m0 = blockIdx.y * 128;

    // Staging: 128 rows x 8 segs of 16B per matrix; 4 (row,seg) pairs/thread.
    const int r_a = tid >> 3;              // row 0..31 (+32*h)
    const int seg = tid & 7;               // 16B segment within 128B (K=64) row

    const uint32_t sbase = (uint32_t)__cvta_generic_to_shared(smem);

    float c[2][8][4];
    #pragma unroll
    for (int i = 0; i < 2; i++)
        #pragma unroll
        for (int j = 0; j < 8; j++)
            #pragma unroll
            for (int q = 0; q < 4; q++) c[i][j][q] = 0.0f;

    auto load_stage = [&](int s) {
        const int term = s >> 5;           // 0,1,2
        const int k0 = (s & 31) << 6;
        const __nv_bfloat16* Ap = (term == 1) ? s_xl : s_xh;
        const __nv_bfloat16* Bp = (term == 2) ? s_wl : s_wh;
        const uint32_t buf = sbase + (uint32_t)(s % 3) * (2 * STAGE_BYTES);
        #pragma unroll
        for (int h = 0; h < 4; h++) {
            const int row = r_a + h * 32;
            const uint32_t doff = (uint32_t)(row * 144 + seg * 16);
            cp_async16(buf + doff,
                       Ap + (size_t)(m0 + row) * HID + k0 + seg * 8);
            cp_async16(buf + STAGE_BYTES + doff,
                       Bp + (size_t)(n0 + row) * HID + k0 + seg * 8);
        }
    };

    load_stage(0); cp_commit();
    load_stage(1); cp_commit();

    uint32_t af[2][2][4];
    uint32_t bf[2][8][2];

    for (int s = 0; s < NSTAGES; ++s) {
        asm volatile("cp.async.wait_group 1;");
        __syncthreads();
        if (s + 2 < NSTAGES) load_stage(s + 2);
        cp_commit();

        const uint32_t Ab = sbase + (uint32_t)(s % 3) * (2 * STAGE_BYTES);
        const uint32_t Bb = Ab + STAGE_BYTES;

        load_frags(Ab, Bb, 0, warp_m, warp_n, lane, af[0], bf[0]);
        #pragma unroll
        for (int ki = 0; ki < 4; ki++) {
            const int cur = ki & 1;
            if (ki < 3)
                load_frags(Ab, Bb, (ki + 1) * 16, warp_m, warp_n, lane,
                           af[cur ^ 1], bf[cur ^ 1]);
            #pragma unroll
            for (int slab = 0; slab < 2; slab++)
                #pragma unroll
                for (int j = 0; j < 8; j++)
                    mma16816(c[slab][j], af[cur][slab], bf[cur][j]);
        }
    }

    // Epilogue: bias + activation; CTA's n-range lies in one gate class
    const int cls = n0 >> 11;                 // 0:i 1:f 2:o
    float* outp = (cls == 0) ? g_i : ((cls == 1) ? g_f : g_o);
    const int cb = n0 & 2047;

    #pragma unroll
    for (int slab = 0; slab < 2; slab++) {
        const int mrow = m0 + warp_m + slab * 16 + (lane >> 2);
        #pragma unroll
        for (int j = 0; j < 8; j++) {
            const int col = warp_n + j * 8 + ((lane & 3) << 1);
            const float b0 = bias[n0 + col], b1 = bias[n0 + col + 1];
            float t0 = c[slab][j][0] + b0, t1 = c[slab][j][1] + b1;
            float t2 = c[slab][j][2] + b0, t3 = c[slab][j][3] + b1;
            float2 v0, v1;
            if (cls == 2) {
                v0.x = 1.0f / (1.0f + expf(-t0));
                v0.y = 1.0f / (1.0f + expf(-t1));
                v1.x = 1.0f / (1.0f + expf(-t2));
                v1.y = 1.0f / (1.0f + expf(-t3));
            } else {
                v0.x = expf(t0); v0.y = expf(t1);
                v1.x = expf(t2); v1.y = expf(t3);
            }
            *(float2*)(outp + (size_t)mrow * HID + cb + col) = v0;
            *(float2*)(outp + (size_t)(mrow + 8) * HID + cb + col) = v1;
        }
    }
}

// ---------------------------------------------------------------------------
// Kernel 2: per-head qkv = x_h @ W_qkv[h] + b_qkv[h]  (SIMT fp32; small)
// ---------------------------------------------------------------------------
__global__ __launch_bounds__(256) void qkv_kernel(
    const float* __restrict__ x, const float* __restrict__ Wq,
    const float* __restrict__ bq)
{
    __shared__ float As2[64][16];
    __shared__ float Bs2[16][64];

    const int tid = threadIdx.x;
    const int tx = tid & 15;
    const int ty = tid >> 4;
    const int head = blockIdx.z;
    const int n0 = blockIdx.x * 64;
    const int m0 = blockIdx.y * 64;

    const int am = m0 + (tid >> 2);
    const int ak = (tid & 3) * 4;
    const int bk = tid >> 4;
    const int bn = (tid & 15) * 4;

    const float* Wh = Wq + (size_t)head * HDIM * 384;

    float acc[4][4] = {};

    for (int k0 = 0; k0 < HDIM; k0 += 16) {
        float4 av = *(const float4*)(x + (size_t)am * HID + head * HDIM + k0 + ak);
        float4 bv = *(const float4*)(Wh + (size_t)(k0 + bk) * 384 + n0 + bn);
        ((float4*)As2)[tid] = av;
        *(float4*)(&Bs2[bk][bn]) = bv;
        __syncthreads();

        #pragma unroll
        for (int kk = 0; kk < 16; kk++) {
            float a0 = As2[ty * 4 + 0][kk];
            float a1 = As2[ty * 4 + 1][kk];
            float a2 = As2[ty * 4 + 2][kk];
            float a3 = As2[ty * 4 + 3][kk];
            float4 b4 = *(float4*)(&Bs2[kk][tx * 4]);
            acc[0][0] += a0 * b4.x; acc[0][1] += a0 * b4.y; acc[0][2] += a0 * b4.z; acc[0][3] += a0 * b4.w;
            acc[1][0] += a1 * b4.x; acc[1][1] += a1 * b4.y; acc[1][2] += a1 * b4.z; acc[1][3] += a1 * b4.w;
            acc[2][0] += a2 * b4.x; acc[2][1] += a2 * b4.y; acc[2][2] += a2 * b4.z; acc[2][3] += a2 * b4.w;
            acc[3][0] += a3 * b4.x; acc[3][1] += a3 * b4.y; acc[3][2] += a3 * b4.z; acc[3][3] += a3 * b4.w;
        }
        __syncthreads();
    }

    const int cls = n0 >> 7;
    const int colb = (n0 & 127) + tx * 4;
    float* outp = (cls == 0) ? g_q : ((cls == 1) ? g_k : g_v);
    const float kscale = 0.08838834764831845f;   // 1/sqrt(128)

    #pragma unroll
    for (int i = 0; i < 4; i++) {
        const int m = m0 + ty * 4 + i;
        float v[4];
        #pragma unroll
        for (int jj = 0; jj < 4; jj++) {
            float t = acc[i][jj] + bq[head * 384 + n0 + tx * 4 + jj];
            if (cls == 1) t *= kscale;
            v[jj] = t;
        }
        float4 rr = make_float4(v[0], v[1], v[2], v[3]);
        *(float4*)(outp + (size_t)m * HID + head * HDIM + colb) = rr;
    }
}

// ---------------------------------------------------------------------------
// Kernel 3: fused state update (memory-roofline bound on C traffic)
// ---------------------------------------------------------------------------
__global__ __launch_bounds__(128) void state_kernel(
    const float* __restrict__ Cin, const float* __restrict__ nin,
    float* __restrict__ out_h, float* __restrict__ out_C,
    float* __restrict__ out_n)
{
    __shared__ float q_s[128], k_s[128];
    __shared__ float f_s[128], a_s[128], o_s[128];
    __shared__ float red[4];
    __shared__ float s_inv;

    const int t = threadIdx.x;
    const int w = t >> 5;
    const int lane = t & 31;
    const int vo = blockIdx.x * HDIM;

    float iv = g_i[vo + t], fv = g_f[vo + t], ov = g_o[vo + t];
    float qv = g_q[vo + t], kv = g_k[vo + t], vv = g_v[vo + t];
    float nv = nin[vo + t];

    float nn = fv * nv + iv * kv;
    out_n[vo + t] = nn;

    q_s[t] = qv; k_s[t] = kv;
    f_s[t] = fv; a_s[t] = iv * vv; o_s[t] = ov;

    float p = nn * qv;
    #pragma unroll
    for (int off = 16; off; off >>= 1) p += __shfl_xor_sync(0xffffffffu, p, off);
    if (lane == 0) red[w] = p;
    __syncthreads();
    if (t == 0) {
        float dot = red[0] + red[1] + red[2] + red[3];
        s_inv = 1.0f / fmaxf(fabsf(dot), 1.0f);
    }
    __syncthreads();
    const float inv = s_inv;

    const float4 q4 = ((const float4*)q_s)[lane];
    const float4 k4 = ((const float4*)k_s)[lane];
    const float4* C4 = (const float4*)(Cin + (size_t)blockIdx.x * HDIM * HDIM);
    float4* O4 = (float4*)(out_C + (size_t)blockIdx.x * HDIM * HDIM);

    #pragma unroll 4
    for (int r = 0; r < 32; r++) {
        const int d = (w << 5) + r;
        float4 cc = C4[d * 32 + lane];
        float part = cc.x * q4.x + cc.y * q4.y + cc.z * q4.z + cc.w * q4.w;
        const float fd = f_s[d], ad = a_s[d];
        float4 cn;
        cn.x = fd * cc.x + ad * k4.x;
        cn.y = fd * cc.y + ad * k4.y;
        cn.z = fd * cc.z + ad * k4.z;
        cn.w = fd * cc.w + ad * k4.w;
        O4[d * 32 + lane] = cn;
        #pragma unroll
        for (int off = 16; off; off >>= 1)
            part += __shfl_xor_sync(0xffffffffu, part, off);
        if (lane == 0) out_h[vo + d] = o_s[d] * part * inv;
    }
}

// ---------------------------------------------------------------------------
// Launch
// ---------------------------------------------------------------------------
extern "C" void kernel_launch(void* const* d_in, const int* in_sizes, int n_in,
                              void* d_out, int out_size)
{
    const float* x     = (const float*)d_in[0];
    const float* C     = (const float*)d_in[2];
    const float* n     = (const float*)d_in[3];
    const float* W_i   = (const float*)d_in[4];
    const float* b_i   = (const float*)d_in[5];
    const float* W_qkv = (const float*)d_in[6];
    const float* b_qkv = (const float*)d_in[7];

    float* out   = (float*)d_out;
    float* out_h = out;
    float* out_C = out + (size_t)BATCH * HID;
    float* out_n = out_C + (size_t)BATCH * NHEAD * HDIM * HDIM;

    cudaFuncSetAttribute(gates_mma_kernel,
                         cudaFuncAttributeMaxDynamicSharedMemorySize, DSMEM);

    split_x_kernel<<<(BATCH * HID) / 256, 256>>>(x);
    splitT_w_kernel<<<dim3(N3 / 32, HID / 32), 256>>>(W_i);
    gates_mma_kernel<<<dim3(N3 / 128, BATCH / 128), 256, DSMEM>>>(b_i);
    qkv_kernel<<<dim3(384 / 64, BATCH / 64, NHEAD), 256>>>(x, W_qkv, b_qkv);
    state_kernel<<<BATCH * NHEAD, 128>>>(C, n, out_h, out_C, out_n);
}

// round 7
// speedup vs baseline: 1.4517x; 1.1318x over previous
#include <cuda_runtime.h>
#include <cuda_bf16.h>
#include <cstdint>
#include <math.h>

#define BATCH 256
#define NHEAD 16
#define HDIM  128
#define HID   2048        // NHEAD * HDIM
#define N3    6144        // 3 * HID

// Scratch: activated gates and projections, [B, HID] each
__device__ __align__(16) float g_i[BATCH * HID];
__device__ __align__(16) float g_f[BATCH * HID];
__device__ __align__(16) float g_o[BATCH * HID];
__device__ __align__(16) float g_q[BATCH * HID];
__device__ __align__(16) float g_k[BATCH * HID];
__device__ __align__(16) float g_v[BATCH * HID];

// Split-precision scratch (bf16 hi/lo)
__device__ __align__(16) __nv_bfloat16 s_xh[BATCH * HID];
__device__ __align__(16) __nv_bfloat16 s_xl[BATCH * HID];
__device__ __align__(16) __nv_bfloat16 s_wh[(size_t)N3 * HID];   // W_i^T [6144,2048]
__device__ __align__(16) __nv_bfloat16 s_wl[(size_t)N3 * HID];
__device__ __align__(16) __nv_bfloat16 s_wqh[NHEAD * 384 * HDIM]; // W_qkv^T [h][384][128]
__device__ __align__(16) __nv_bfloat16 s_wql[NHEAD * 384 * HDIM];

// ---------------------------------------------------------------------------
// Split x -> bf16 hi/lo
// ---------------------------------------------------------------------------
__global__ __launch_bounds__(256) void split_x_kernel(const float* __restrict__ x)
{
    int idx = blockIdx.x * 256 + threadIdx.x;
    float v = x[idx];
    __nv_bfloat16 hi = __float2bfloat16(v);
    float lo = v - __bfloat162float(hi);
    s_xh[idx] = hi;
    s_xl[idx] = __float2bfloat16(lo);
}

// ---------------------------------------------------------------------------
// Split + transpose W_i [2048,6144] -> Wt hi/lo [6144,2048]
// ---------------------------------------------------------------------------
__global__ __launch_bounds__(256) void splitT_w_kernel(const float* __restrict__ W)
{
    __shared__ float tile[32][33];
    const int n0 = blockIdx.x * 32;
    const int k0 = blockIdx.y * 32;
    const int tx = threadIdx.x & 31;
    const int ty = threadIdx.x >> 5;   // 0..7

    #pragma unroll
    for (int j = 0; j < 4; j++)
        tile[ty + j * 8][tx] = W[(size_t)(k0 + ty + j * 8) * N3 + n0 + tx];
    __syncthreads();

    #pragma unroll
    for (int j = 0; j < 4; j++) {
        float v = tile[tx][ty + j * 8];
        __nv_bfloat16 hi = __float2bfloat16(v);
        float lo = v - __bfloat162float(hi);
        size_t o = (size_t)(n0 + ty + j * 8) * HID + k0 + tx;
        s_wh[o] = hi;
        s_wl[o] = __float2bfloat16(lo);
    }
}

// ---------------------------------------------------------------------------
// Split + transpose W_qkv [h][128][384] -> [h][384][128] hi/lo
// ---------------------------------------------------------------------------
__global__ __launch_bounds__(256) void splitT_wq_kernel(const float* __restrict__ Wq)
{
    __shared__ float tile[32][33];
    const int n0 = blockIdx.x * 32;     // 0..352
    const int k0 = blockIdx.y * 32;     // 0..96
    const int h  = blockIdx.z;
    const int tx = threadIdx.x & 31;
    const int ty = threadIdx.x >> 5;

    #pragma unroll
    for (int j = 0; j < 4; j++)
        tile[ty + j * 8][tx] = Wq[((size_t)h * HDIM + k0 + ty + j * 8) * 384 + n0 + tx];
    __syncthreads();

    #pragma unroll
    for (int j = 0; j < 4; j++) {
        float v = tile[tx][ty + j * 8];
        __nv_bfloat16 hi = __float2bfloat16(v);
        float lo = v - __bfloat162float(hi);
        size_t o = ((size_t)h * 384 + n0 + ty + j * 8) * HDIM + k0 + tx;
        s_wqh[o] = hi;
        s_wql[o] = __float2bfloat16(lo);
    }
}

// ---------------------------------------------------------------------------
// PTX helpers (sm_80-compatible: cp.async + ldmatrix + mma.sync)
// ---------------------------------------------------------------------------
__device__ __forceinline__ void cp_async16(uint32_t dst, const void* src) {
    asm volatile("cp.async.cg.shared.global [%0], [%1], 16;"
                 :: "r"(dst), "l"(src));
}
__device__ __forceinline__ void cp_commit() {
    asm volatile("cp.async.commit_group;");
}

__device__ __forceinline__ void ldm_x4(uint32_t* r, uint32_t addr) {
    asm volatile("ldmatrix.sync.aligned.m8n8.x4.shared.b16 {%0,%1,%2,%3}, [%4];"
                 : "=r"(r[0]), "=r"(r[1]), "=r"(r[2]), "=r"(r[3]) : "r"(addr));
}

__device__ __forceinline__ void mma16816(float* c, const uint32_t* a, const uint32_t* b) {
    asm volatile(
        "mma.sync.aligned.m16n8k16.row.col.f32.bf16.bf16.f32 "
        "{%0,%1,%2,%3}, {%4,%5,%6,%7}, {%8,%9}, {%0,%1,%2,%3};"
        : "+f"(c[0]), "+f"(c[1]), "+f"(c[2]), "+f"(c[3])
        : "r"(a[0]), "r"(a[1]), "r"(a[2]), "r"(a[3]), "r"(b[0]), "r"(b[1]));
}

#define SST 72                    // bf16 elems per smem row (144B = 9*16B)

// ===========================================================================
// Gates GEMM: D = Xh@Wh^T + Xl@Wh^T + Xh@Wl^T  (bf16x3 split precision)
// CTA tile 128x96 (128 CTAs -> 86% SM fill), 256 threads,
// 8 warps 4Mx2N, warp tile 32x48. BK=64, 3-stage cp.async ring.
// ===========================================================================
#define GA_STAGE (128 * SST * 2)      // 18432
#define GB_STAGE (96 * SST * 2)       // 13824
#define G_STAGE (GA_STAGE + GB_STAGE) // 32256
#define G_NSTAGES 96
#define G_DSMEM (3 * G_STAGE)         // 96768

__global__ __launch_bounds__(256, 1) void gates_mma_kernel(const float* __restrict__ bias)
{
    extern __shared__ __nv_bfloat16 smem[];

    const int tid = threadIdx.x;
    const int lane = tid & 31;
    const int wid = tid >> 5;
    const int warp_m = (wid & 3) * 32;     // 0,32,64,96
    const int warp_n = (wid >> 2) * 48;    // 0,48
    const int n0 = blockIdx.x * 96;
    const int m0 = blockIdx.y * 128;

    const int r_s = tid >> 3;              // 0..31
    const int seg = tid & 7;

    const uint32_t sbase = (uint32_t)__cvta_generic_to_shared(smem);

    float c[2][6][4];
    #pragma unroll
    for (int i = 0; i < 2; i++)
        #pragma unroll
        for (int j = 0; j < 6; j++)
            #pragma unroll
            for (int q = 0; q < 4; q++) c[i][j][q] = 0.0f;

    auto load_stage = [&](int s) {
        const int term = s >> 5;
        const int k0 = (s & 31) << 6;
        const __nv_bfloat16* Ap = (term == 1) ? s_xl : s_xh;
        const __nv_bfloat16* Bp = (term == 2) ? s_wl : s_wh;
        const uint32_t buf = sbase + (uint32_t)(s % 3) * G_STAGE;
        #pragma unroll
        for (int h = 0; h < 4; h++) {
            const int row = r_s + h * 32;
            cp_async16(buf + (uint32_t)(row * 144 + seg * 16),
                       Ap + (size_t)(m0 + row) * HID + k0 + seg * 8);
        }
        #pragma unroll
        for (int h = 0; h < 3; h++) {
            const int row = r_s + h * 32;
            cp_async16(buf + GA_STAGE + (uint32_t)(row * 144 + seg * 16),
                       Bp + (size_t)(n0 + row) * HID + k0 + seg * 8);
        }
    };

    auto load_frags = [&](uint32_t Ab, uint32_t Bb, int kk,
                          uint32_t af[2][4], uint32_t bf[6][2]) {
        #pragma unroll
        for (int slab = 0; slab < 2; slab++) {
            const int row = warp_m + slab * 16 + (lane & 15);
            const int col = kk + ((lane >> 4) << 3);
            ldm_x4(af[slab], Ab + (uint32_t)(row * SST + col) * 2);
        }
        const int g = lane >> 3;
        #pragma unroll
        for (int nb = 0; nb < 3; nb++) {
            const int nrow = warp_n + nb * 16 + ((g >> 1) << 3) + (lane & 7);
            const int col = kk + ((g & 1) << 3);
            uint32_t rr[4];
            ldm_x4(rr, Bb + (uint32_t)(nrow * SST + col) * 2);
            bf[nb * 2 + 0][0] = rr[0]; bf[nb * 2 + 0][1] = rr[1];
            bf[nb * 2 + 1][0] = rr[2]; bf[nb * 2 + 1][1] = rr[3];
        }
    };

    load_stage(0); cp_commit();
    load_stage(1); cp_commit();

    uint32_t af[2][2][4];
    uint32_t bf[2][6][2];

    for (int s = 0; s < G_NSTAGES; ++s) {
        asm volatile("cp.async.wait_group 1;");
        __syncthreads();
        if (s + 2 < G_NSTAGES) load_stage(s + 2);
        cp_commit();

        const uint32_t Ab = sbase + (uint32_t)(s % 3) * G_STAGE;
        const uint32_t Bb = Ab + GA_STAGE;

        load_frags(Ab, Bb, 0, af[0], bf[0]);
        #pragma unroll
        for (int ki = 0; ki < 4; ki++) {
            const int cur = ki & 1;
            if (ki < 3)
                load_frags(Ab, Bb, (ki + 1) * 16, af[cur ^ 1], bf[cur ^ 1]);
            #pragma unroll
            for (int slab = 0; slab < 2; slab++)
                #pragma unroll
                for (int j = 0; j < 6; j++)
                    mma16816(c[slab][j], af[cur][slab], bf[cur][j]);
        }
    }

    // Epilogue: per-column gate class (tile may straddle class boundaries)
    #pragma unroll
    for (int slab = 0; slab < 2; slab++) {
        const int mrow = m0 + warp_m + slab * 16 + (lane >> 2);
        #pragma unroll
        for (int j = 0; j < 6; j++) {
            const int col = n0 + warp_n + j * 8 + ((lane & 3) << 1);
            const int cls = col >> 11;          // 0:i 1:f 2:o (pair never straddles)
            float* outp = (cls == 0) ? g_i : ((cls == 1) ? g_f : g_o);
            const int cb = col & 2047;
            const float b0 = bias[col], b1 = bias[col + 1];
            float t0 = c[slab][j][0] + b0, t1 = c[slab][j][1] + b1;
            float t2 = c[slab][j][2] + b0, t3 = c[slab][j][3] + b1;
            float2 v0, v1;
            if (cls == 2) {
                v0.x = 1.0f / (1.0f + expf(-t0));
                v0.y = 1.0f / (1.0f + expf(-t1));
                v1.x = 1.0f / (1.0f + expf(-t2));
                v1.y = 1.0f / (1.0f + expf(-t3));
            } else {
                v0.x = expf(t0); v0.y = expf(t1);
                v1.x = expf(t2); v1.y = expf(t3);
            }
            *(float2*)(outp + (size_t)mrow * HID + cb) = v0;
            *(float2*)(outp + (size_t)(mrow + 8) * HID + cb) = v1;
        }
    }
}

// ===========================================================================
// QKV GEMM (per-head, bf16x3): M=256, N=384, K=128 per head.
// CTA tile 128x128, grid (3, 2, 16) = 96 CTAs, 6 stages of BK=64.
// ===========================================================================
#define Q_STAGE (2 * 128 * SST * 2)   // 36864 (A + B, both 128 rows)
#define Q_NSTAGES 6
#define Q_DSMEM (3 * Q_STAGE)         // 110592

__global__ __launch_bounds__(256, 1) void qkv_mma_kernel(const float* __restrict__ bq)
{
    extern __shared__ __nv_bfloat16 smem[];

    const int tid = threadIdx.x;
    const int lane = tid & 31;
    const int wid = tid >> 5;
    const int warp_m = (wid & 3) * 32;
    const int warp_n = (wid >> 2) * 64;
    const int n0 = blockIdx.x * 128;       // 0,128,256 (of 384)
    const int m0 = blockIdx.y * 128;
    const int head = blockIdx.z;

    const int r_s = tid >> 3;
    const int seg = tid & 7;

    const uint32_t sbase = (uint32_t)__cvta_generic_to_shared(smem);

    float c[2][8][4];
    #pragma unroll
    for (int i = 0; i < 2; i++)
        #pragma unroll
        for (int j = 0; j < 8; j++)
            #pragma unroll
            for (int q = 0; q < 4; q++) c[i][j][q] = 0.0f;

    auto load_stage = [&](int s) {
        const int term = s >> 1;           // 0,1,2
        const int k0 = (s & 1) << 6;
        const __nv_bfloat16* Ap = (term == 1) ? s_xl : s_xh;
        const __nv_bfloat16* Bp = (term == 2) ? s_wql : s_wqh;
        const uint32_t buf = sbase + (uint32_t)(s % 3) * Q_STAGE;
        #pragma unroll
        for (int h = 0; h < 4; h++) {
            const int row = r_s + h * 32;
            const uint32_t doff = (uint32_t)(row * 144 + seg * 16);
            cp_async16(buf + doff,
                       Ap + (size_t)(m0 + row) * HID + head * HDIM + k0 + seg * 8);
            cp_async16(buf + (uint32_t)(128 * 144) + doff,
                       Bp + ((size_t)head * 384 + n0 + row) * HDIM + k0 + seg * 8);
        }
    };

    auto load_frags = [&](uint32_t Ab, uint32_t Bb, int kk,
                          uint32_t af[2][4], uint32_t bf[8][2]) {
        #pragma unroll
        for (int slab = 0; slab < 2; slab++) {
            const int row = warp_m + slab * 16 + (lane & 15);
            const int col = kk + ((lane >> 4) << 3);
            ldm_x4(af[slab], Ab + (uint32_t)(row * SST + col) * 2);
        }
        const int g = lane >> 3;
        #pragma unroll
        for (int nb = 0; nb < 4; nb++) {
            const int nrow = warp_n + nb * 16 + ((g >> 1) << 3) + (lane & 7);
            const int col = kk + ((g & 1) << 3);
            uint32_t rr[4];
            ldm_x4(rr, Bb + (uint32_t)(nrow * SST + col) * 2);
            bf[nb * 2 + 0][0] = rr[0]; bf[nb * 2 + 0][1] = rr[1];
            bf[nb * 2 + 1][0] = rr[2]; bf[nb * 2 + 1][1] = rr[3];
        }
    };

    load_stage(0); cp_commit();
    load_stage(1); cp_commit();

    uint32_t af[2][2][4];
    uint32_t bf[2][8][2];

    for (int s = 0; s < Q_NSTAGES; ++s) {
        asm volatile("cp.async.wait_group 1;");
        __syncthreads();
        if (s + 2 < Q_NSTAGES) load_stage(s + 2);
        cp_commit();

        const uint32_t Ab = sbase + (uint32_t)(s % 3) * Q_STAGE;
        const uint32_t Bb = Ab + (uint32_t)(128 * 144);

        load_frags(Ab, Bb, 0, af[0], bf[0]);
        #pragma unroll
        for (int ki = 0; ki < 4; ki++) {
            const int cur = ki & 1;
            if (ki < 3)
                load_frags(Ab, Bb, (ki + 1) * 16, af[cur ^ 1], bf[cur ^ 1]);
            #pragma unroll
            for (int slab = 0; slab < 2; slab++)
                #pragma unroll
                for (int j = 0; j < 8; j++)
                    mma16816(c[slab][j], af[cur][slab], bf[cur][j]);
        }
    }

    const float kscale = 0.08838834764831845f;   // 1/sqrt(128)

    #pragma unroll
    for (int slab = 0; slab < 2; slab++) {
        const int mrow = m0 + warp_m + slab * 16 + (lane >> 2);
        #pragma unroll
        for (int j = 0; j < 8; j++) {
            const int ncol = n0 + warp_n + j * 8 + ((lane & 3) << 1);  // 0..383
            const int cls = ncol >> 7;          // 0:q 1:k 2:v
            float* outp = (cls == 0) ? g_q : ((cls == 1) ? g_k : g_v);
            const int colb = ncol & 127;
            const float b0 = bq[head * 384 + ncol];
            const float b1 = bq[head * 384 + ncol + 1];
            float t0 = c[slab][j][0] + b0, t1 = c[slab][j][1] + b1;
            float t2 = c[slab][j][2] + b0, t3 = c[slab][j][3] + b1;
            if (cls == 1) { t0 *= kscale; t1 *= kscale; t2 *= kscale; t3 *= kscale; }
            *(float2*)(outp + (size_t)mrow * HID + head * HDIM + colb) =
                make_float2(t0, t1);
            *(float2*)(outp + (size_t)(mrow + 8) * HID + head * HDIM + colb) =
                make_float2(t2, t3);
        }
    }
}

// ---------------------------------------------------------------------------
// Fused state update (memory-roofline bound on C traffic)
// ---------------------------------------------------------------------------
__global__ __launch_bounds__(128) void state_kernel(
    const float* __restrict__ Cin, const float* __restrict__ nin,
    float* __restrict__ out_h, float* __restrict__ out_C,
    float* __restrict__ out_n)
{
    __shared__ float q_s[128], k_s[128];
    __shared__ float f_s[128], a_s[128], o_s[128];
    __shared__ float red[4];
    __shared__ float s_inv;

    const int t = threadIdx.x;
    const int w = t >> 5;
    const int lane = t & 31;
    const int vo = blockIdx.x * HDIM;

    float iv = g_i[vo + t], fv = g_f[vo + t], ov = g_o[vo + t];
    float qv = g_q[vo + t], kv = g_k[vo + t], vv = g_v[vo + t];
    float nv = nin[vo + t];

    float nn = fv * nv + iv * kv;
    out_n[vo + t] = nn;

    q_s[t] = qv; k_s[t] = kv;
    f_s[t] = fv; a_s[t] = iv * vv; o_s[t] = ov;

    float p = nn * qv;
    #pragma unroll
    for (int off = 16; off; off >>= 1) p += __shfl_xor_sync(0xffffffffu, p, off);
    if (lane == 0) red[w] = p;
    __syncthreads();
    if (t == 0) {
        float dot = red[0] + red[1] + red[2] + red[3];
        s_inv = 1.0f / fmaxf(fabsf(dot), 1.0f);
    }
    __syncthreads();
    const float inv = s_inv;

    const float4 q4 = ((const float4*)q_s)[lane];
    const float4 k4 = ((const float4*)k_s)[lane];
    const float4* C4 = (const float4*)(Cin + (size_t)blockIdx.x * HDIM * HDIM);
    float4* O4 = (float4*)(out_C + (size_t)blockIdx.x * HDIM * HDIM);

    #pragma unroll 4
    for (int r = 0; r < 32; r++) {
        const int d = (w << 5) + r;
        float4 cc = C4[d * 32 + lane];
        float part = cc.x * q4.x + cc.y * q4.y + cc.z * q4.z + cc.w * q4.w;
        const float fd = f_s[d], ad = a_s[d];
        float4 cn;
        cn.x = fd * cc.x + ad * k4.x;
        cn.y = fd * cc.y + ad * k4.y;
        cn.z = fd * cc.z + ad * k4.z;
        cn.w = fd * cc.w + ad * k4.w;
        O4[d * 32 + lane] = cn;
        #pragma unroll
        for (int off = 16; off; off >>= 1)
            part += __shfl_xor_sync(0xffffffffu, part, off);
        if (lane == 0) out_h[vo + d] = o_s[d] * part * inv;
    }
}

// ---------------------------------------------------------------------------
// Launch
// ---------------------------------------------------------------------------
extern "C" void kernel_launch(void* const* d_in, const int* in_sizes, int n_in,
                              void* d_out, int out_size)
{
    const float* x     = (const float*)d_in[0];
    const float* C     = (const float*)d_in[2];
    const float* n     = (const float*)d_in[3];
    const float* W_i   = (const float*)d_in[4];
    const float* b_i   = (const float*)d_in[5];
    const float* W_qkv = (const float*)d_in[6];
    const float* b_qkv = (const float*)d_in[7];

    float* out   = (float*)d_out;
    float* out_h = out;
    float* out_C = out + (size_t)BATCH * HID;
    float* out_n = out_C + (size_t)BATCH * NHEAD * HDIM * HDIM;

    cudaFuncSetAttribute(gates_mma_kernel,
                         cudaFuncAttributeMaxDynamicSharedMemorySize, G_DSMEM);
    cudaFuncSetAttribute(qkv_mma_kernel,
                         cudaFuncAttributeMaxDynamicSharedMemorySize, Q_DSMEM);

    split_x_kernel<<<(BATCH * HID) / 256, 256>>>(x);
    splitT_w_kernel<<<dim3(N3 / 32, HID / 32), 256>>>(W_i);
    splitT_wq_kernel<<<dim3(384 / 32, HDIM / 32, NHEAD), 256>>>(W_qkv);
    gates_mma_kernel<<<dim3(N3 / 96, BATCH / 128), 256, G_DSMEM>>>(b_i);
    qkv_mma_kernel<<<dim3(384 / 128, BATCH / 128, NHEAD), 256, Q_DSMEM>>>(b_qkv);
    state_kernel<<<BATCH * NHEAD, 128>>>(C, n, out_h, out_C, out_n);
}